// round 12
// baseline (speedup 1.0000x reference)
#include <cuda_runtime.h>
#include <cstdint>
#include <cstddef>

// Problem constants
#define B_  8
#define H_  16
#define L_  4096
#define D_  64
#define M_  8      // log_lk
#define C_  5
#define CTX_ELEMS ((size_t)B_*H_*L_*D_)   // 33554432

typedef unsigned long long u64;

// Scratch (device globals; no allocation allowed)
__device__ float g_partK[8*128*512];   // [ls][bh][m][d] partials (2MB)
__device__ float g_partV[8*128*512];
__device__ float g_Ks[B_*H_*M_*D_];    // 65536
__device__ float g_attn[(size_t)H_*L_*M_];  // 524288
__device__ float g_dot[64*C_*8];       // [blk][c][warp] dot partials
__device__ int   g_zero;
__device__ float g_loss;

#define FFMA2(acc, a, b) \
    asm("fma.rn.f32x2 %0, %1, %2, %0;" : "+l"(acc) : "l"(a), "l"(b))

// ---------------------------------------------------------------------------
// Shrink one array (K or V): partial over an L-slab of 512.
// grid (128 bh, 8 ls), 256 threads = (lsub 16) x (dq 16).
// Whole 512-row W slab staged ONCE (32KB dup pairs, 1 barrier), then a single
// uninterrupted 32-iter main loop. occ 4 for latency hiding.
// ---------------------------------------------------------------------------
__global__ __launch_bounds__(256, 4)
void shrink_one(const float* __restrict__ src, const float* __restrict__ W, int kv)
{
    __shared__ float sbuf[8192];     // 32KB: W dup pairs [512 ll][8 m]; reused for reduction
    float2* sW = reinterpret_cast<float2*>(sbuf);

    const int tid  = threadIdx.x;
    const int bh   = blockIdx.x;
    const int ls   = blockIdx.y;       // 0..7
    const int dq   = tid & 15;
    const int lsub = tid >> 4;
    const int l0   = ls * 512;

    // stage full W slab: 4096 values, 16 per thread
    for (int j = tid; j < 4096; j += 256) {
        int m = j >> 9, ll = j & 511;
        float w = W[m*L_ + l0 + ll];
        sW[ll*8 + m] = make_float2(w, w);
    }
    __syncthreads();

    u64 a2[8][2];
#pragma unroll
    for (int m = 0; m < 8; ++m) { a2[m][0] = 0ull; a2[m][1] = 0ull; }

    const ulonglong2* S2 = reinterpret_cast<const ulonglong2*>(src + ((size_t)bh*L_ + l0)*D_);
#pragma unroll 8
    for (int j = 0; j < 32; ++j) {
        int ll = (j << 4) + lsub;
        ulonglong2 kk = S2[ll*16 + dq];
#pragma unroll
        for (int m = 0; m < 8; ++m) {
            u64 w = *reinterpret_cast<const u64*>(&sW[ll*8 + m]);
            FFMA2(a2[m][0], kk.x, w);
            FFMA2(a2[m][1], kk.y, w);
        }
    }
    __syncthreads();

    // cross-lsub reduction (reuse sbuf as float4[2048] = 32KB)
    float4* red = reinterpret_cast<float4*>(sbuf);
#pragma unroll
    for (int m = 0; m < 8; ++m) {
        float2 f0 = *reinterpret_cast<float2*>(&a2[m][0]);
        float2 f1 = *reinterpret_cast<float2*>(&a2[m][1]);
        red[lsub*128 + m*16 + dq] = make_float4(f0.x, f0.y, f1.x, f1.y);
    }
    __syncthreads();
    if (tid < 128) {
        float4 s = make_float4(0.f,0.f,0.f,0.f);
#pragma unroll
        for (int g = 0; g < 16; ++g) {
            float4 v = red[g*128 + tid];
            s.x += v.x; s.y += v.y; s.z += v.z; s.w += v.w;
        }
        float4* dst = reinterpret_cast<float4*>(kv ? g_partV : g_partK);
        dst[(size_t)(ls*128 + bh)*128 + tid] = s;
    }
}

// ---------------------------------------------------------------------------
// Reduce 8 K-partial slabs -> g_Ks (+bias), FUSED with cluster dot partials.
// 64 blocks x 256 threads. Block blk covers f4 range [blk*256, blk*256+256),
// all within batch b = blk>>3. Per-warp dot partials -> g_dot (deterministic).
// ---------------------------------------------------------------------------
__global__ __launch_bounds__(256, 8)
void reduce_k(const float* __restrict__ bias, const float* __restrict__ Wpc)
{
    const int tid = threadIdx.x;
    const int blk = blockIdx.x;
    const int i = blk * 256 + tid;                   // float4 index, 0..16383
    const int m = (i >> 4) & 7;
    const float4* P = reinterpret_cast<const float4*>(g_partK);
    float4 s = make_float4(0.f,0.f,0.f,0.f);
#pragma unroll
    for (int ls = 0; ls < 8; ++ls) {
        float4 a = P[ls*16384 + i];
        s.x += a.x; s.y += a.y; s.z += a.z; s.w += a.w;
    }
    float b = bias[m];
    s.x += b; s.y += b; s.z += b; s.w += b;
    reinterpret_cast<float4*>(g_Ks)[i] = s;

    // cluster dot partials: flat index within batch = i & 2047
    const int ib = i & 2047;
    const float4* W4 = reinterpret_cast<const float4*>(Wpc);
    float d[C_];
#pragma unroll
    for (int c = 0; c < C_; ++c) {
        float4 w = W4[c*2048 + ib];
        d[c] = s.x*w.x + s.y*w.y + s.z*w.z + s.w*w.w;
    }
#pragma unroll
    for (int c = 0; c < C_; ++c) {
        float v = d[c];
#pragma unroll
        for (int off = 16; off; off >>= 1) v += __shfl_xor_sync(0xffffffffu, v, off);
        if ((tid & 31) == 0) g_dot[(blk*C_ + c)*8 + (tid >> 5)] = v;
    }
}

// ---------------------------------------------------------------------------
// Cluster finalize: sum partials, softmaxes, loss, g_zero, loss -> out tail.
// 1 block, 64 threads. Small weights prefetched to smem in parallel first.
// ---------------------------------------------------------------------------
__global__ __launch_bounds__(64, 1)
void cluster_fin(const float* __restrict__ bpc,
                 const float* __restrict__ Wq,  const float* __restrict__ bq,
                 const float* __restrict__ Wk,  const float* __restrict__ bk,
                 float* __restrict__ out, long long out_size)
{
    const int tid = threadIdx.x;
    __shared__ float zred[B_*C_];
    __shared__ float sWq[25], sWk[25], sbq[C_], sbk[C_], sbpc[C_];
    if (tid < 25) { sWq[tid] = Wq[tid]; sWk[tid] = Wk[tid]; }
    if (tid >= 32 && tid < 37) {
        int c = tid - 32;
        sbq[c] = bq[c]; sbk[c] = bk[c]; sbpc[c] = bpc[c];
    }
    if (tid < B_*C_) {
        // tid -> (b,c); sum over 8 sub-blocks of b and 8 warps
        int b = tid / C_, c = tid % C_;
        float s = 0.f;
#pragma unroll
        for (int sb = 0; sb < 8; ++sb)
#pragma unroll
            for (int w = 0; w < 8; ++w)
                s += g_dot[((b*8 + sb)*C_ + c)*8 + w];
        zred[tid] = s;
    }
    __syncthreads();

    if (tid == 0) {
        float z[B_][C_], cq[B_][C_], ck[B_][C_];
        for (int b = 0; b < B_; ++b)
            for (int c = 0; c < C_; ++c) {
                float v = zred[b*C_ + c] + sbpc[c];
                z[b][c] = v > 0.f ? v : 0.f;
            }
        for (int b = 0; b < B_; ++b) {
            float lq[C_], lk_[C_];
            for (int c = 0; c < C_; ++c) {
                float sq = sbq[c], sk = sbk[c];
                for (int j = 0; j < C_; ++j) {
                    sq = fmaf(z[b][j], sWq[c*C_ + j], sq);
                    sk = fmaf(z[b][j], sWk[c*C_ + j], sk);
                }
                lq[c] = sq; lk_[c] = sk;
            }
            float mq = lq[0], mk = lk_[0];
            for (int c = 1; c < C_; ++c) { mq = fmaxf(mq, lq[c]); mk = fmaxf(mk, lk_[c]); }
            float sq = 0.f, sk = 0.f;
            for (int c = 0; c < C_; ++c) { lq[c] = expf(lq[c]-mq); sq += lq[c];
                                           lk_[c] = expf(lk_[c]-mk); sk += lk_[c]; }
            for (int c = 0; c < C_; ++c) { cq[b][c] = lq[c]/sq; ck[b][c] = lk_[c]/sk; }
        }
        float mu[C_], sigma[C_];
        for (int c = 0; c < C_; ++c) {
            float s = 0.f, sc = 0.f;
            for (int b = 0; b < B_; ++b) { s += cq[b][c]; sc += ck[b][c]; }
            mu[c] = s / B_;
            float mck = sc / B_;
            float var = 0.f;
            for (int b = 0; b < B_; ++b) { float dlt = ck[b][c]-mck; var += dlt*dlt; }
            var /= (B_ - 1);
            sigma[c] = log1pf(expf(sqrtf(var)));
        }
        const float HL2PI = 0.9189385332046727f;
        float sumlp = 0.f;
        for (int b = 0; b < B_; ++b)
            for (int c = 0; c < C_; ++c) {
                float t = (ck[b][c] - mu[c]) / sigma[c];
                sumlp += -0.5f*t*t - logf(sigma[c]) - HL2PI;
            }
        float mean_lp = sumlp / (B_*C_);
        float ce = 0.f;
        for (int b = 0; b < B_; ++b) {
            float mx = cq[b][0];
            for (int c = 1; c < C_; ++c) mx = fmaxf(mx, cq[b][c]);
            float se = 0.f;
            for (int c = 0; c < C_; ++c) se += expf(cq[b][c]-mx);
            float lse = mx + logf(se);
            float s = 0.f;
            for (int c = 0; c < C_; ++c) s += cq[b][c] * (cq[b][c] - lse);
            ce += -s;
        }
        ce /= B_;
        float loss = -mean_lp + ce;
        g_loss = loss;
        int ind0 = 0; float best = cq[0][0];
        for (int c = 1; c < C_; ++c) if (cq[0][c] > best) { best = cq[0][c]; ind0 = c; }
        g_zero = (ind0 >= 1) ? 1 : 0;
        for (long long j = (long long)CTX_ELEMS; j < out_size; ++j) out[j] = loss;
    }
}

// ---------------------------------------------------------------------------
// attn[h,q,k] — 2 threads per q (split d). grid 512 = (h, 32 qt), 256 thr.
// ---------------------------------------------------------------------------
__global__ __launch_bounds__(256, 8)
void attn_kernel(const float* __restrict__ Q)
{
    __shared__ float4 sKs4[128];   // 2KB, Ks[0,h]
    const int tid = threadIdx.x;
    const int h   = blockIdx.x >> 5;
    const int qt  = blockIdx.x & 31;
    if (tid < 128)
        sKs4[tid] = reinterpret_cast<const float4*>(g_Ks)[(size_t)h*128 + tid];
    __syncthreads();

    const int ql   = tid >> 1;           // 0..127
    const int half = tid & 1;
    const int q    = qt*128 + ql;
    const float4* Qrow = reinterpret_cast<const float4*>(Q + ((size_t)h*L_ + q)*D_) + half*8;

    u64 acc2[8][2];
#pragma unroll
    for (int k = 0; k < 8; ++k) { acc2[k][0] = 0ull; acc2[k][1] = 0ull; }
#pragma unroll
    for (int d4 = 0; d4 < 8; ++d4) {
        float4 qv = Qrow[d4];
        ulonglong2 qu = *reinterpret_cast<const ulonglong2*>(&qv);
#pragma unroll
        for (int k = 0; k < 8; ++k) {
            float4 kv = sKs4[k*16 + half*8 + d4];
            ulonglong2 ku = *reinterpret_cast<const ulonglong2*>(&kv);
            FFMA2(acc2[k][0], qu.x, ku.x);
            FFMA2(acc2[k][1], qu.y, ku.y);
        }
    }
    float base[8];
#pragma unroll
    for (int k = 0; k < 8; ++k) {
        float2 a = *reinterpret_cast<float2*>(&acc2[k][0]);
        float2 b = *reinterpret_cast<float2*>(&acc2[k][1]);
        float part = a.x + a.y + b.x + b.y;
        float other = __shfl_xor_sync(0xffffffffu, part, 1);
        base[k] = (part + other) * 0.125f;
    }
    if (half == 0) {
        float s[8], mx = -1e30f;
#pragma unroll
        for (int k = 0; k < 8; ++k) { s[k] = (k <= q) ? -1e9f : base[k]; mx = fmaxf(mx, s[k]); }
        float sum = 0.f, e[8];
#pragma unroll
        for (int k = 0; k < 8; ++k) { e[k] = expf(s[k]-mx); sum += e[k]; }
        float rs = 8.f / sum;
        float f[8];
#pragma unroll
        for (int k = 0; k < 8; ++k) f[k] = e[k] * rs;
        if (g_zero) {
#pragma unroll
            for (int k = 0; k < 8; ++k) {
                float bv;
                if (q >= 7)      bv = 1.f;
                else if (k > q)  bv = 8.f / (float)(7 - q);
                else             bv = 0.f;
                f[k] = fmaxf(f[k], bv);
            }
        }
        mx = f[0];
#pragma unroll
        for (int k = 1; k < 8; ++k) mx = fmaxf(mx, f[k]);
        sum = 0.f;
#pragma unroll
        for (int k = 0; k < 8; ++k) { e[k] = expf(f[k]-mx); sum += e[k]; }
        float inv = 1.f / sum;
        float4* dst = reinterpret_cast<float4*>(g_attn + ((size_t)h*L_ + q)*M_);
        dst[0] = make_float4(e[0]*inv, e[1]*inv, e[2]*inv, e[3]*inv);
        dst[1] = make_float4(e[4]*inv, e[5]*inv, e[6]*inv, e[7]*inv);
    }
}

// ---------------------------------------------------------------------------
// Context via smem tiles + TMA bulk stores. grid 1024 = (b, h, qq of 8),
// each block a 512q x 64d slab (8 tiles of 64q/16KB, double-buffered).
// Reduces V-partials + bias inline.
// ---------------------------------------------------------------------------
__global__ __launch_bounds__(256, 3)
void ctx_kernel(float* __restrict__ out, const float* __restrict__ bsv)
{
    __shared__ float4 sV4[M_*16];          // 2KB  Vs[b,h]
    __shared__ float4 sA4[64*2];           // 2KB  attn subtile (64 q x 8 k)
    __shared__ float  sOut[2][4096];       // 32KB double-buffered output tiles

    const int tid = threadIdx.x;
    const int qq  = blockIdx.x & 7;
    const int h   = (blockIdx.x >> 3) & 15;
    const int b   = blockIdx.x >> 7;

    // Inline V reduction: Vs[b,h] = sum_ls partV[ls][bh] + bsv[m]
    if (tid < 128) {
        const float4* P = reinterpret_cast<const float4*>(g_partV);
        const int bh = b*H_ + h;
        float4 s = make_float4(0.f,0.f,0.f,0.f);
#pragma unroll
        for (int ls = 0; ls < 8; ++ls) {
            float4 v = P[(size_t)(ls*128 + bh)*128 + tid];
            s.x += v.x; s.y += v.y; s.z += v.z; s.w += v.w;
        }
        float bm = bsv[tid >> 4];
        s.x += bm; s.y += bm; s.z += bm; s.w += bm;
        sV4[tid] = s;
    }

    const int dq = tid & 15;
    const int q0 = tid >> 4;
    const size_t outBase = (((size_t)b*H_ + h) * L_ + (size_t)qq*512) * D_;
    const float4* gA4 = reinterpret_cast<const float4*>(g_attn) +
                        ((size_t)h * L_ + (size_t)qq*512) * 2;

    for (int s = 0; s < 8; ++s) {
        const int p = s & 1;
        if (tid == 0 && s >= 2)
            asm volatile("cp.async.bulk.wait_group 1;" ::: "memory");
        __syncthreads();
        if (tid < 128)
            sA4[tid] = gA4[(size_t)s*128 + tid];
        __syncthreads();

        float4* o4 = reinterpret_cast<float4*>(sOut[p]);
#pragma unroll
        for (int i = 0; i < 4; ++i) {
            int ql = i*16 + q0;
            float4 a0 = sA4[ql*2], a1 = sA4[ql*2 + 1];
            float aw[8] = {a0.x, a0.y, a0.z, a0.w, a1.x, a1.y, a1.z, a1.w};
            float4 acc = make_float4(0.f, 0.f, 0.f, 0.f);
#pragma unroll
            for (int k = 0; k < 8; ++k) {
                float4 v = sV4[k*16 + dq];
                acc.x = fmaf(aw[k], v.x, acc.x);
                acc.y = fmaf(aw[k], v.y, acc.y);
                acc.z = fmaf(aw[k], v.z, acc.z);
                acc.w = fmaf(aw[k], v.w, acc.w);
            }
            o4[ql*16 + dq] = acc;
        }
        __syncthreads();
        if (tid == 0) {
            asm volatile("fence.proxy.async.shared::cta;" ::: "memory");
            unsigned int saddr = (unsigned int)__cvta_generic_to_shared(&sOut[p][0]);
            const float* gdst = out + outBase + (size_t)s * 4096;
            asm volatile("cp.async.bulk.global.shared::cta.bulk_group [%0], [%1], %2;"
                         :: "l"(gdst), "r"(saddr), "r"(16384) : "memory");
            asm volatile("cp.async.bulk.commit_group;" ::: "memory");
        }
    }
    if (tid == 0)
        asm volatile("cp.async.bulk.wait_group 0;" ::: "memory");
}

// ---------------------------------------------------------------------------
extern "C" void kernel_launch(void* const* d_in, const int* in_sizes, int n_in,
                              void* d_out, int out_size)
{
    const float* Q   = (const float*)d_in[0];
    const float* K   = (const float*)d_in[1];
    const float* V   = (const float*)d_in[2];
    const float* Wsk = (const float*)d_in[3];
    const float* bsk = (const float*)d_in[4];
    const float* Wsv = (const float*)d_in[5];
    const float* bsv = (const float*)d_in[6];
    const float* Wpc = (const float*)d_in[7];
    const float* bpc = (const float*)d_in[8];
    const float* Wq  = (const float*)d_in[9];
    const float* bq  = (const float*)d_in[10];
    const float* Wk  = (const float*)d_in[11];
    const float* bk  = (const float*)d_in[12];
    float* out = (float*)d_out;

    // One-time side-stream/event setup (created on the eager pre-capture call).
    static cudaStream_t s2 = 0;
    static cudaEvent_t  e0 = 0, e1 = 0;
    static int inited = 0;
    if (!inited) {
        if (cudaStreamCreateWithFlags(&s2, cudaStreamNonBlocking) != cudaSuccess) s2 = 0;
        if (s2) {
            if (cudaEventCreateWithFlags(&e0, cudaEventDisableTiming) != cudaSuccess ||
                cudaEventCreateWithFlags(&e1, cudaEventDisableTiming) != cudaSuccess) {
                s2 = 0;
            }
        }
        inited = 1;
    }

    // K path on capture stream
    shrink_one<<<dim3(128, 8), 256>>>(K, Wsk, 0);
    if (s2) cudaEventRecord(e0, 0);
    reduce_k<<<64, 256>>>(bsk, Wpc);
    cluster_fin<<<1, 64>>>(bpc, Wq, bq, Wk, bk, out, (long long)out_size);
    attn_kernel<<<512, 256>>>(Q);

    // V path forked onto s2 (starts after K-shrink; overlaps cluster+attn)
    if (s2) {
        cudaStreamWaitEvent(s2, e0, 0);
        shrink_one<<<dim3(128, 8), 256, 0, s2>>>(V, Wsv, 1);
        cudaEventRecord(e1, s2);
        cudaStreamWaitEvent(0, e1, 0);
    } else {
        shrink_one<<<dim3(128, 8), 256>>>(V, Wsv, 1);
    }

    // ctx consumes V partials directly (inline reduce+bias)
    ctx_kernel<<<1024, 256>>>(out, bsv);
}

// round 17
// speedup vs baseline: 1.1653x; 1.1653x over previous
#include <cuda_runtime.h>
#include <cstdint>
#include <cstddef>

// Problem constants
#define B_  8
#define H_  16
#define L_  4096
#define D_  64
#define M_  8      // log_lk
#define C_  5
#define CTX_ELEMS ((size_t)B_*H_*L_*D_)   // 33554432

typedef unsigned long long u64;

// Scratch (device globals; no allocation allowed)
__device__ float g_partK[8*128*512];   // [ls][bh][m][d] partials (2MB)
__device__ float g_partV[8*128*512];
__device__ float g_Ks[B_*H_*M_*D_];    // 65536
__device__ float g_attn[(size_t)H_*L_*M_];  // 524288
__device__ float g_dot[64*C_*8];       // [blk][c][warp] dot partials
__device__ int   g_zero;
__device__ float g_loss;

#define FFMA2(acc, a, b) \
    asm("fma.rn.f32x2 %0, %1, %2, %0;" : "+l"(acc) : "l"(a), "l"(b))

// ---------------------------------------------------------------------------
// Shrink one array (K or V): partial over an L-slab of 512 (R11/R6 version —
// two-stage W staging, occ 3; the proven 125.6us configuration).
// grid (128 bh, 8 ls), 256 threads = (lsub 16) x (dq 16).
// ---------------------------------------------------------------------------
__global__ __launch_bounds__(256, 3)
void shrink_one(const float* __restrict__ src, const float* __restrict__ W, int kv)
{
    __shared__ char sbuf[32768];     // [0,16K): W pairs; reused for reduction
    float2* sW = reinterpret_cast<float2*>(sbuf);   // [256 ll][8 m]

    const int tid  = threadIdx.x;
    const int bh   = blockIdx.x;
    const int ls   = blockIdx.y;       // 0..7
    const int dq   = tid & 15;
    const int lsub = tid >> 4;
    const int l0   = ls * 512;

    u64 a2[8][2];
#pragma unroll
    for (int m = 0; m < 8; ++m) { a2[m][0] = 0ull; a2[m][1] = 0ull; }

    for (int outer = 0; outer < 2; ++outer) {
        const int lb = l0 + outer * 256;
        for (int j = tid; j < 2048; j += 256) {
            int m = j >> 8, ll = j & 255;
            float w = W[m*L_ + lb + ll];
            sW[ll*8 + m] = make_float2(w, w);
        }
        __syncthreads();

        const ulonglong2* S2 = reinterpret_cast<const ulonglong2*>(src + ((size_t)bh*L_ + lb)*D_);
#pragma unroll 8
        for (int j = 0; j < 16; ++j) {
            int ll = (j << 4) + lsub;
            ulonglong2 kk = S2[ll*16 + dq];
#pragma unroll
            for (int m = 0; m < 8; ++m) {
                u64 w = *reinterpret_cast<const u64*>(&sW[ll*8 + m]);
                FFMA2(a2[m][0], kk.x, w);
                FFMA2(a2[m][1], kk.y, w);
            }
        }
        __syncthreads();
    }

    // cross-lsub reduction (reuse sbuf as float4[2048] = 32KB)
    float4* red = reinterpret_cast<float4*>(sbuf);
#pragma unroll
    for (int m = 0; m < 8; ++m) {
        float2 f0 = *reinterpret_cast<float2*>(&a2[m][0]);
        float2 f1 = *reinterpret_cast<float2*>(&a2[m][1]);
        red[lsub*128 + m*16 + dq] = make_float4(f0.x, f0.y, f1.x, f1.y);
    }
    __syncthreads();
    if (tid < 128) {
        float4 s = make_float4(0.f,0.f,0.f,0.f);
#pragma unroll
        for (int g = 0; g < 16; ++g) {
            float4 v = red[g*128 + tid];
            s.x += v.x; s.y += v.y; s.z += v.z; s.w += v.w;
        }
        float4* dst = reinterpret_cast<float4*>(kv ? g_partV : g_partK);
        dst[(size_t)(ls*128 + bh)*128 + tid] = s;
    }
}

// ---------------------------------------------------------------------------
// Reduce 8 K-partial slabs -> g_Ks (+bias), FUSED with cluster dot partials.
// 64 blocks x 256 threads. Block blk covers f4 range [blk*256, blk*256+256),
// all within batch b = blk>>3. Per-warp dot partials -> g_dot (deterministic).
// ---------------------------------------------------------------------------
__global__ __launch_bounds__(256, 8)
void reduce_k(const float* __restrict__ bias, const float* __restrict__ Wpc)
{
    const int tid = threadIdx.x;
    const int blk = blockIdx.x;
    const int i = blk * 256 + tid;                   // float4 index, 0..16383
    const int m = (i >> 4) & 7;
    const float4* P = reinterpret_cast<const float4*>(g_partK);
    float4 s = make_float4(0.f,0.f,0.f,0.f);
#pragma unroll
    for (int ls = 0; ls < 8; ++ls) {
        float4 a = P[ls*16384 + i];
        s.x += a.x; s.y += a.y; s.z += a.z; s.w += a.w;
    }
    float b = bias[m];
    s.x += b; s.y += b; s.z += b; s.w += b;
    reinterpret_cast<float4*>(g_Ks)[i] = s;

    // cluster dot partials: flat index within batch = i & 2047
    const int ib = i & 2047;
    const float4* W4 = reinterpret_cast<const float4*>(Wpc);
    float d[C_];
#pragma unroll
    for (int c = 0; c < C_; ++c) {
        float4 w = W4[c*2048 + ib];
        d[c] = s.x*w.x + s.y*w.y + s.z*w.z + s.w*w.w;
    }
#pragma unroll
    for (int c = 0; c < C_; ++c) {
        float v = d[c];
#pragma unroll
        for (int off = 16; off; off >>= 1) v += __shfl_xor_sync(0xffffffffu, v, off);
        if ((tid & 31) == 0) g_dot[(blk*C_ + c)*8 + (tid >> 5)] = v;
    }
}

// ---------------------------------------------------------------------------
// Cluster finalize: sum partials, softmaxes, loss, g_zero, loss -> out tail.
// 1 block, 64 threads. Small weights prefetched to smem in parallel first.
// ---------------------------------------------------------------------------
__global__ __launch_bounds__(64, 1)
void cluster_fin(const float* __restrict__ bpc,
                 const float* __restrict__ Wq,  const float* __restrict__ bq,
                 const float* __restrict__ Wk,  const float* __restrict__ bk,
                 float* __restrict__ out, long long out_size)
{
    const int tid = threadIdx.x;
    __shared__ float zred[B_*C_];
    __shared__ float sWq[25], sWk[25], sbq[C_], sbk[C_], sbpc[C_];
    if (tid < 25) { sWq[tid] = Wq[tid]; sWk[tid] = Wk[tid]; }
    if (tid >= 32 && tid < 37) {
        int c = tid - 32;
        sbq[c] = bq[c]; sbk[c] = bk[c]; sbpc[c] = bpc[c];
    }
    if (tid < B_*C_) {
        int b = tid / C_, c = tid % C_;
        float s = 0.f;
#pragma unroll
        for (int sb = 0; sb < 8; ++sb)
#pragma unroll
            for (int w = 0; w < 8; ++w)
                s += g_dot[((b*8 + sb)*C_ + c)*8 + w];
        zred[tid] = s;
    }
    __syncthreads();

    if (tid == 0) {
        float z[B_][C_], cq[B_][C_], ck[B_][C_];
        for (int b = 0; b < B_; ++b)
            for (int c = 0; c < C_; ++c) {
                float v = zred[b*C_ + c] + sbpc[c];
                z[b][c] = v > 0.f ? v : 0.f;
            }
        for (int b = 0; b < B_; ++b) {
            float lq[C_], lk_[C_];
            for (int c = 0; c < C_; ++c) {
                float sq = sbq[c], sk = sbk[c];
                for (int j = 0; j < C_; ++j) {
                    sq = fmaf(z[b][j], sWq[c*C_ + j], sq);
                    sk = fmaf(z[b][j], sWk[c*C_ + j], sk);
                }
                lq[c] = sq; lk_[c] = sk;
            }
            float mq = lq[0], mk = lk_[0];
            for (int c = 1; c < C_; ++c) { mq = fmaxf(mq, lq[c]); mk = fmaxf(mk, lk_[c]); }
            float sq = 0.f, sk = 0.f;
            for (int c = 0; c < C_; ++c) { lq[c] = expf(lq[c]-mq); sq += lq[c];
                                           lk_[c] = expf(lk_[c]-mk); sk += lk_[c]; }
            for (int c = 0; c < C_; ++c) { cq[b][c] = lq[c]/sq; ck[b][c] = lk_[c]/sk; }
        }
        float mu[C_], sigma[C_];
        for (int c = 0; c < C_; ++c) {
            float s = 0.f, sc = 0.f;
            for (int b = 0; b < B_; ++b) { s += cq[b][c]; sc += ck[b][c]; }
            mu[c] = s / B_;
            float mck = sc / B_;
            float var = 0.f;
            for (int b = 0; b < B_; ++b) { float dlt = ck[b][c]-mck; var += dlt*dlt; }
            var /= (B_ - 1);
            sigma[c] = log1pf(expf(sqrtf(var)));
        }
        const float HL2PI = 0.9189385332046727f;
        float sumlp = 0.f;
        for (int b = 0; b < B_; ++b)
            for (int c = 0; c < C_; ++c) {
                float t = (ck[b][c] - mu[c]) / sigma[c];
                sumlp += -0.5f*t*t - logf(sigma[c]) - HL2PI;
            }
        float mean_lp = sumlp / (B_*C_);
        float ce = 0.f;
        for (int b = 0; b < B_; ++b) {
            float mx = cq[b][0];
            for (int c = 1; c < C_; ++c) mx = fmaxf(mx, cq[b][c]);
            float se = 0.f;
            for (int c = 0; c < C_; ++c) se += expf(cq[b][c]-mx);
            float lse = mx + logf(se);
            float s = 0.f;
            for (int c = 0; c < C_; ++c) s += cq[b][c] * (cq[b][c] - lse);
            ce += -s;
        }
        ce /= B_;
        float loss = -mean_lp + ce;
        g_loss = loss;
        int ind0 = 0; float best = cq[0][0];
        for (int c = 1; c < C_; ++c) if (cq[0][c] > best) { best = cq[0][c]; ind0 = c; }
        g_zero = (ind0 >= 1) ? 1 : 0;
        for (long long j = (long long)CTX_ELEMS; j < out_size; ++j) out[j] = loss;
    }
}

// ---------------------------------------------------------------------------
// attn[h,q,k] — 2 threads per q (split d). grid 512 = (h, 32 qt), 256 thr.
// ---------------------------------------------------------------------------
__global__ __launch_bounds__(256, 8)
void attn_kernel(const float* __restrict__ Q)
{
    __shared__ float4 sKs4[128];   // 2KB, Ks[0,h]
    const int tid = threadIdx.x;
    const int h   = blockIdx.x >> 5;
    const int qt  = blockIdx.x & 31;
    if (tid < 128)
        sKs4[tid] = reinterpret_cast<const float4*>(g_Ks)[(size_t)h*128 + tid];
    __syncthreads();

    const int ql   = tid >> 1;           // 0..127
    const int half = tid & 1;
    const int q    = qt*128 + ql;
    const float4* Qrow = reinterpret_cast<const float4*>(Q + ((size_t)h*L_ + q)*D_) + half*8;

    u64 acc2[8][2];
#pragma unroll
    for (int k = 0; k < 8; ++k) { acc2[k][0] = 0ull; acc2[k][1] = 0ull; }
#pragma unroll
    for (int d4 = 0; d4 < 8; ++d4) {
        float4 qv = Qrow[d4];
        ulonglong2 qu = *reinterpret_cast<const ulonglong2*>(&qv);
#pragma unroll
        for (int k = 0; k < 8; ++k) {
            float4 kv = sKs4[k*16 + half*8 + d4];
            ulonglong2 ku = *reinterpret_cast<const ulonglong2*>(&kv);
            FFMA2(acc2[k][0], qu.x, ku.x);
            FFMA2(acc2[k][1], qu.y, ku.y);
        }
    }
    float base[8];
#pragma unroll
    for (int k = 0; k < 8; ++k) {
        float2 a = *reinterpret_cast<float2*>(&acc2[k][0]);
        float2 b = *reinterpret_cast<float2*>(&acc2[k][1]);
        float part = a.x + a.y + b.x + b.y;
        float other = __shfl_xor_sync(0xffffffffu, part, 1);
        base[k] = (part + other) * 0.125f;
    }
    if (half == 0) {
        float s[8], mx = -1e30f;
#pragma unroll
        for (int k = 0; k < 8; ++k) { s[k] = (k <= q) ? -1e9f : base[k]; mx = fmaxf(mx, s[k]); }
        float sum = 0.f, e[8];
#pragma unroll
        for (int k = 0; k < 8; ++k) { e[k] = expf(s[k]-mx); sum += e[k]; }
        float rs = 8.f / sum;
        float f[8];
#pragma unroll
        for (int k = 0; k < 8; ++k) f[k] = e[k] * rs;
        if (g_zero) {
#pragma unroll
            for (int k = 0; k < 8; ++k) {
                float bv;
                if (q >= 7)      bv = 1.f;
                else if (k > q)  bv = 8.f / (float)(7 - q);
                else             bv = 0.f;
                f[k] = fmaxf(f[k], bv);
            }
        }
        mx = f[0];
#pragma unroll
        for (int k = 1; k < 8; ++k) mx = fmaxf(mx, f[k]);
        sum = 0.f;
#pragma unroll
        for (int k = 0; k < 8; ++k) { e[k] = expf(f[k]-mx); sum += e[k]; }
        float inv = 1.f / sum;
        float4* dst = reinterpret_cast<float4*>(g_attn + ((size_t)h*L_ + q)*M_);
        dst[0] = make_float4(e[0]*inv, e[1]*inv, e[2]*inv, e[3]*inv);
        dst[1] = make_float4(e[4]*inv, e[5]*inv, e[6]*inv, e[7]*inv);
    }
}

// ---------------------------------------------------------------------------
// Context via smem tiles + TMA bulk stores. grid 1024 = (b, h, qq of 8),
// each block a 512q x 64d slab (8 tiles of 64q/16KB, double-buffered).
// Reduces V-partials + bias inline.
// ---------------------------------------------------------------------------
__global__ __launch_bounds__(256, 3)
void ctx_kernel(float* __restrict__ out, const float* __restrict__ bsv)
{
    __shared__ float4 sV4[M_*16];          // 2KB  Vs[b,h]
    __shared__ float4 sA4[64*2];           // 2KB  attn subtile (64 q x 8 k)
    __shared__ float  sOut[2][4096];       // 32KB double-buffered output tiles

    const int tid = threadIdx.x;
    const int qq  = blockIdx.x & 7;
    const int h   = (blockIdx.x >> 3) & 15;
    const int b   = blockIdx.x >> 7;

    // Inline V reduction: Vs[b,h] = sum_ls partV[ls][bh] + bsv[m]
    if (tid < 128) {
        const float4* P = reinterpret_cast<const float4*>(g_partV);
        const int bh = b*H_ + h;
        float4 s = make_float4(0.f,0.f,0.f,0.f);
#pragma unroll
        for (int ls = 0; ls < 8; ++ls) {
            float4 v = P[(size_t)(ls*128 + bh)*128 + tid];
            s.x += v.x; s.y += v.y; s.z += v.z; s.w += v.w;
        }
        float bm = bsv[tid >> 4];
        s.x += bm; s.y += bm; s.z += bm; s.w += bm;
        sV4[tid] = s;
    }

    const int dq = tid & 15;
    const int q0 = tid >> 4;
    const size_t outBase = (((size_t)b*H_ + h) * L_ + (size_t)qq*512) * D_;
    const float4* gA4 = reinterpret_cast<const float4*>(g_attn) +
                        ((size_t)h * L_ + (size_t)qq*512) * 2;

    for (int s = 0; s < 8; ++s) {
        const int p = s & 1;
        if (tid == 0 && s >= 2)
            asm volatile("cp.async.bulk.wait_group 1;" ::: "memory");
        __syncthreads();
        if (tid < 128)
            sA4[tid] = gA4[(size_t)s*128 + tid];
        __syncthreads();

        float4* o4 = reinterpret_cast<float4*>(sOut[p]);
#pragma unroll
        for (int i = 0; i < 4; ++i) {
            int ql = i*16 + q0;
            float4 a0 = sA4[ql*2], a1 = sA4[ql*2 + 1];
            float aw[8] = {a0.x, a0.y, a0.z, a0.w, a1.x, a1.y, a1.z, a1.w};
            float4 acc = make_float4(0.f, 0.f, 0.f, 0.f);
#pragma unroll
            for (int k = 0; k < 8; ++k) {
                float4 v = sV4[k*16 + dq];
                acc.x = fmaf(aw[k], v.x, acc.x);
                acc.y = fmaf(aw[k], v.y, acc.y);
                acc.z = fmaf(aw[k], v.z, acc.z);
                acc.w = fmaf(aw[k], v.w, acc.w);
            }
            o4[ql*16 + dq] = acc;
        }
        __syncthreads();
        if (tid == 0) {
            asm volatile("fence.proxy.async.shared::cta;" ::: "memory");
            unsigned int saddr = (unsigned int)__cvta_generic_to_shared(&sOut[p][0]);
            const float* gdst = out + outBase + (size_t)s * 4096;
            asm volatile("cp.async.bulk.global.shared::cta.bulk_group [%0], [%1], %2;"
                         :: "l"(gdst), "r"(saddr), "r"(16384) : "memory");
            asm volatile("cp.async.bulk.commit_group;" ::: "memory");
        }
    }
    if (tid == 0)
        asm volatile("cp.async.bulk.wait_group 0;" ::: "memory");
}

// ---------------------------------------------------------------------------
extern "C" void kernel_launch(void* const* d_in, const int* in_sizes, int n_in,
                              void* d_out, int out_size)
{
    const float* Q   = (const float*)d_in[0];
    const float* K   = (const float*)d_in[1];
    const float* V   = (const float*)d_in[2];
    const float* Wsk = (const float*)d_in[3];
    const float* bsk = (const float*)d_in[4];
    const float* Wsv = (const float*)d_in[5];
    const float* bsv = (const float*)d_in[6];
    const float* Wpc = (const float*)d_in[7];
    const float* bpc = (const float*)d_in[8];
    const float* Wq  = (const float*)d_in[9];
    const float* bq  = (const float*)d_in[10];
    const float* Wk  = (const float*)d_in[11];
    const float* bk  = (const float*)d_in[12];
    float* out = (float*)d_out;

    // One-time side-stream/event setup (created on the eager pre-capture call).
    static cudaStream_t s2 = 0;
    static cudaEvent_t  e0 = 0, e1 = 0;
    static int inited = 0;
    if (!inited) {
        if (cudaStreamCreateWithFlags(&s2, cudaStreamNonBlocking) != cudaSuccess) s2 = 0;
        if (s2) {
            if (cudaEventCreateWithFlags(&e0, cudaEventDisableTiming) != cudaSuccess ||
                cudaEventCreateWithFlags(&e1, cudaEventDisableTiming) != cudaSuccess) {
                s2 = 0;
            }
        }
        inited = 1;
    }

    // K path on capture stream
    shrink_one<<<dim3(128, 8), 256>>>(K, Wsk, 0);
    if (s2) cudaEventRecord(e0, 0);
    reduce_k<<<64, 256>>>(bsk, Wpc);
    cluster_fin<<<1, 64>>>(bpc, Wq, bq, Wk, bk, out, (long long)out_size);
    attn_kernel<<<512, 256>>>(Q);

    // V path forked onto s2 (starts after K-shrink; overlaps cluster+attn)
    if (s2) {
        cudaStreamWaitEvent(s2, e0, 0);
        shrink_one<<<dim3(128, 8), 256, 0, s2>>>(V, Wsv, 1);
        cudaEventRecord(e1, s2);
        cudaStreamWaitEvent(0, e1, 0);
    } else {
        shrink_one<<<dim3(128, 8), 256>>>(V, Wsv, 1);
    }

    // ctx consumes V partials directly (inline reduce+bias)
    ctx_kernel<<<1024, 256>>>(out, bsv);
}